// round 1
// baseline (speedup 1.0000x reference)
#include <cuda_runtime.h>
#include <math.h>

// Problem constants (fixed by the dataset)
#define BB 2
#define LL 2048
#define DD 1024
#define HH 16
#define DH 64
#define HALF 64          // window_size / 2
#define NTOK (BB * LL)   // 4096

// Scratch (no cudaMalloc allowed)
__device__ float g_xn[NTOK * DD];        // 16 MB
__device__ float g_qkv[NTOK * 3 * DD];   // 48 MB
__device__ float g_attn[NTOK * DD];      // 16 MB

// ---------------------------------------------------------------------------
// RMSNorm: one block per row (1024 floats), 256 threads, float4 per thread
// ---------------------------------------------------------------------------
__global__ void __launch_bounds__(256) rmsnorm_kernel(
    const float* __restrict__ x, const float* __restrict__ w,
    float* __restrict__ o)
{
    int row = blockIdx.x;
    const float4* xr = (const float4*)(x + (size_t)row * DD);
    float4* orow = (float4*)(o + (size_t)row * DD);
    const float4* wr = (const float4*)w;
    int t = threadIdx.x;

    float4 v = xr[t];
    float ss = v.x * v.x + v.y * v.y + v.z * v.z + v.w * v.w;
#pragma unroll
    for (int off = 16; off > 0; off >>= 1)
        ss += __shfl_xor_sync(0xffffffffu, ss, off);

    __shared__ float red[8];
    __shared__ float stot;
    if ((t & 31) == 0) red[t >> 5] = ss;
    __syncthreads();
    if (t == 0) {
        float tot = 0.f;
#pragma unroll
        for (int i = 0; i < 8; i++) tot += red[i];
        stot = tot;
    }
    __syncthreads();

    float inv = rsqrtf(stot * (1.0f / DD) + 1e-6f);
    float4 wv = wr[t];
    float4 ov;
    ov.x = v.x * inv * wv.x;
    ov.y = v.y * inv * wv.y;
    ov.z = v.z * inv * wv.z;
    ov.w = v.w * inv * wv.w;
    orow[t] = ov;
}

// ---------------------------------------------------------------------------
// SGEMM: C[M,N] = A[M,K] @ W[N,K]^T (+ optional residual R[M,N])
// 64x64 block tile, BK=16, 256 threads, 4x4 microtile per thread.
// M,N,K all multiples of tile sizes here (4096 x {3072,1024} x 1024).
// ---------------------------------------------------------------------------
template <bool RES>
__global__ void __launch_bounds__(256) sgemm_tn(
    const float* __restrict__ A, const float* __restrict__ W,
    float* __restrict__ C, const float* __restrict__ R,
    int N, int K)
{
    const int BM = 64, BN = 64, BK = 16;
    __shared__ float As[BK][68];  // [k][m], pad keeps float4 alignment + few conflicts
    __shared__ float Bs[BK][68];  // [k][n]

    int m0 = blockIdx.y * BM;
    int n0 = blockIdx.x * BN;
    int tid = threadIdx.x;
    int ty = tid >> 4;       // 0..15
    int tx = tid & 15;       // 0..15
    int lr = tid >> 2;       // 0..63 : row (A) / col (W) for loads
    int ls = (tid & 3) * 4;  // k-segment start

    const float* Aptr = A + (size_t)(m0 + lr) * K + ls;
    const float* Wptr = W + (size_t)(n0 + lr) * K + ls;

    float acc[4][4] = {};

    for (int k0 = 0; k0 < K; k0 += BK) {
        float4 av = *(const float4*)(Aptr + k0);
        float4 wv = *(const float4*)(Wptr + k0);
        As[ls + 0][lr] = av.x; As[ls + 1][lr] = av.y;
        As[ls + 2][lr] = av.z; As[ls + 3][lr] = av.w;
        Bs[ls + 0][lr] = wv.x; Bs[ls + 1][lr] = wv.y;
        Bs[ls + 2][lr] = wv.z; Bs[ls + 3][lr] = wv.w;
        __syncthreads();

#pragma unroll
        for (int kk = 0; kk < BK; kk++) {
            float4 a = *(const float4*)&As[kk][ty * 4];
            float4 b = *(const float4*)&Bs[kk][tx * 4];
            float ar[4] = {a.x, a.y, a.z, a.w};
            float br[4] = {b.x, b.y, b.z, b.w};
#pragma unroll
            for (int i = 0; i < 4; i++)
#pragma unroll
                for (int j = 0; j < 4; j++)
                    acc[i][j] = fmaf(ar[i], br[j], acc[i][j]);
        }
        __syncthreads();
    }

#pragma unroll
    for (int i = 0; i < 4; i++) {
        int row = m0 + ty * 4 + i;
        float4 cv = make_float4(acc[i][0], acc[i][1], acc[i][2], acc[i][3]);
        if (RES) {
            float4 rv = *(const float4*)(R + (size_t)row * N + n0 + tx * 4);
            cv.x += rv.x; cv.y += rv.y; cv.z += rv.z; cv.w += rv.w;
        }
        *(float4*)(C + (size_t)row * N + n0 + tx * 4) = cv;
    }
}

// ---------------------------------------------------------------------------
// Windowed attention.
// One block per (64-query tile, head, batch). Key union window = 192 keys.
// Dynamic smem: Qs[64][64] + Kt[64][193] + Vs[192][64] + S[64][192]
// ---------------------------------------------------------------------------
#define ATTN_SMEM ((64 * 64 + 64 * 193 + 192 * 64 + 64 * 192) * 4)

__global__ void __launch_bounds__(256) attn_kernel(
    const float* __restrict__ qkv, float* __restrict__ o)
{
    extern __shared__ float sm[];
    float* Qs = sm;                 // [r][d]   stride 64
    float* Kt = Qs + 64 * 64;       // [d][jj]  stride 193
    float* Vs = Kt + 64 * 193;      // [jj][d]  stride 64
    float* S  = Vs + 192 * 64;      // [r][jj]  stride 192

    const int q0 = blockIdx.x * 64;
    const int h  = blockIdx.y;
    const int b  = blockIdx.z;
    const int tid = threadIdx.x;

    // ---- load Q, K (transposed), V ----
    {
        int c4 = (tid & 15) * 4;
        int rb = tid >> 4;  // 0..15
#pragma unroll
        for (int p = 0; p < 4; p++) {
            int r = p * 16 + rb;
            float4 v = *(const float4*)(qkv +
                (size_t)(b * LL + q0 + r) * (3 * DD) + h * DH + c4);
            *(float4*)(Qs + r * 64 + c4) = v;
        }
#pragma unroll
        for (int p = 0; p < 12; p++) {
            int jj = p * 16 + rb;
            int j = q0 - HALF + jj;
            float4 kv = make_float4(0.f, 0.f, 0.f, 0.f);
            float4 vv = make_float4(0.f, 0.f, 0.f, 0.f);
            if (j >= 0 && j < LL) {
                const float* base = qkv + (size_t)(b * LL + j) * (3 * DD) + h * DH + c4;
                kv = *(const float4*)(base + DD);
                vv = *(const float4*)(base + 2 * DD);
            }
            Kt[(c4 + 0) * 193 + jj] = kv.x;
            Kt[(c4 + 1) * 193 + jj] = kv.y;
            Kt[(c4 + 2) * 193 + jj] = kv.z;
            Kt[(c4 + 3) * 193 + jj] = kv.w;
            *(float4*)(Vs + jj * 64 + c4) = vv;
        }
    }
    __syncthreads();

    // ---- scores S[64][192] = (Q @ K^T) / 8, masked ----
    {
        int rowg = tid >> 4;   // rows rowg*4..+3
        int colg = tid & 15;   // cols colg*12..+11
        float acc[4][12] = {};
#pragma unroll 4
        for (int d = 0; d < 64; d++) {
            float qv[4];
#pragma unroll
            for (int i = 0; i < 4; i++) qv[i] = Qs[(rowg * 4 + i) * 64 + d];
            float kva[12];
#pragma unroll
            for (int c = 0; c < 12; c++) kva[c] = Kt[d * 193 + colg * 12 + c];
#pragma unroll
            for (int i = 0; i < 4; i++)
#pragma unroll
                for (int c = 0; c < 12; c++)
                    acc[i][c] = fmaf(qv[i], kva[c], acc[i][c]);
        }
        const float scale = 0.125f;  // 1/sqrt(64)
#pragma unroll
        for (int i = 0; i < 4; i++) {
            int r = rowg * 4 + i;
#pragma unroll
            for (int c = 0; c < 12; c++) {
                int jj = colg * 12 + c;
                int j = q0 - HALF + jj;
                bool valid = (j >= 0) && (j < LL) && (jj >= r) && (jj <= r + 2 * HALF);
                S[r * 192 + jj] = valid ? acc[i][c] * scale : -1e30f;
            }
        }
    }
    __syncthreads();

    // ---- softmax per row (8 warps x 8 rows) ----
    {
        int w = tid >> 5, lane = tid & 31;
#pragma unroll
        for (int rr = 0; rr < 8; rr++) {
            int r = w * 8 + rr;
            float vv[6];
            float mx = -1e30f;
#pragma unroll
            for (int s = 0; s < 6; s++) {
                vv[s] = S[r * 192 + lane + 32 * s];
                mx = fmaxf(mx, vv[s]);
            }
#pragma unroll
            for (int off = 16; off > 0; off >>= 1)
                mx = fmaxf(mx, __shfl_xor_sync(0xffffffffu, mx, off));
            float sum = 0.f;
#pragma unroll
            for (int s = 0; s < 6; s++) {
                vv[s] = __expf(vv[s] - mx);
                sum += vv[s];
            }
#pragma unroll
            for (int off = 16; off > 0; off >>= 1)
                sum += __shfl_xor_sync(0xffffffffu, sum, off);
            float inv = 1.0f / sum;
#pragma unroll
            for (int s = 0; s < 6; s++)
                S[r * 192 + lane + 32 * s] = vv[s] * inv;
        }
    }
    __syncthreads();

    // ---- O[64][64] = P @ V ----
    {
        int ty = tid >> 4, tx = tid & 15;
        float acc[4][4] = {};
#pragma unroll 2
        for (int jj = 0; jj < 192; jj++) {
            float p[4];
#pragma unroll
            for (int i = 0; i < 4; i++) p[i] = S[(ty * 4 + i) * 192 + jj];
            float4 v = *(const float4*)(Vs + jj * 64 + tx * 4);
            float vr[4] = {v.x, v.y, v.z, v.w};
#pragma unroll
            for (int i = 0; i < 4; i++)
#pragma unroll
                for (int j = 0; j < 4; j++)
                    acc[i][j] = fmaf(p[i], vr[j], acc[i][j]);
        }
#pragma unroll
        for (int i = 0; i < 4; i++) {
            int r = q0 + ty * 4 + i;
            *(float4*)(o + (size_t)(b * LL + r) * DD + h * DH + tx * 4) =
                make_float4(acc[i][0], acc[i][1], acc[i][2], acc[i][3]);
        }
    }
}

// ---------------------------------------------------------------------------
extern "C" void kernel_launch(void* const* d_in, const int* in_sizes, int n_in,
                              void* d_out, int out_size)
{
    const float* x     = (const float*)d_in[0];
    const float* wnorm = (const float*)d_in[1];
    const float* wqkv  = (const float*)d_in[2];
    const float* wout  = (const float*)d_in[3];
    float* out = (float*)d_out;

    float* xn   = nullptr;
    float* qkv  = nullptr;
    float* attn = nullptr;
    cudaGetSymbolAddress((void**)&xn,   g_xn);
    cudaGetSymbolAddress((void**)&qkv,  g_qkv);
    cudaGetSymbolAddress((void**)&attn, g_attn);

    cudaFuncSetAttribute(attn_kernel,
                         cudaFuncAttributeMaxDynamicSharedMemorySize, ATTN_SMEM);

    // 1) RMSNorm
    rmsnorm_kernel<<<NTOK, 256>>>(x, wnorm, xn);

    // 2) QKV projection: [4096,1024] @ [3072,1024]^T -> [4096,3072]
    {
        dim3 grid(3 * DD / 64, NTOK / 64);
        sgemm_tn<false><<<grid, 256>>>(xn, wqkv, qkv, nullptr, 3 * DD, DD);
    }

    // 3) Windowed attention
    {
        dim3 grid(LL / 64, HH, BB);
        attn_kernel<<<grid, 256, ATTN_SMEM>>>(qkv, attn);
    }

    // 4) Output projection + residual: [4096,1024] @ [1024,1024]^T + x
    {
        dim3 grid(DD / 64, NTOK / 64);
        sgemm_tn<true><<<grid, 256>>>(attn, wout, out, x, DD, DD);
    }
}

// round 6
// speedup vs baseline: 1.2286x; 1.2286x over previous
#include <cuda_runtime.h>
#include <math.h>

// Problem constants (fixed by the dataset)
#define BB 2
#define LL 2048
#define DD 1024
#define HH 16
#define DH 64
#define HALF 64          // window_size / 2
#define NTOK (BB * LL)   // 4096

// Scratch (no cudaMalloc allowed)
__device__ float g_xn[NTOK * DD];        // 16 MB
__device__ float g_qkv[NTOK * 3 * DD];   // 48 MB
__device__ float g_attn[NTOK * DD];      // 16 MB

// ---------------------------------------------------------------------------
// Packed fp32x2 helpers (sm_103a FFMA2 path; exact fp32 numerics per lane)
// ---------------------------------------------------------------------------
__device__ __forceinline__ unsigned long long pack2(float lo, float hi) {
    unsigned long long r;
    asm("mov.b64 %0, {%1, %2};" : "=l"(r) : "f"(lo), "f"(hi));
    return r;
}
__device__ __forceinline__ void unpack2(unsigned long long v, float& lo, float& hi) {
    asm("mov.b64 {%0, %1}, %2;" : "=f"(lo), "=f"(hi) : "l"(v));
}
__device__ __forceinline__ void fma2(unsigned long long& d,
                                     unsigned long long a, unsigned long long b) {
    asm("fma.rn.f32x2 %0, %1, %2, %0;" : "+l"(d) : "l"(a), "l"(b));
}

// ---------------------------------------------------------------------------
// RMSNorm: one block per row (1024 floats), 256 threads, float4 per thread
// ---------------------------------------------------------------------------
__global__ void __launch_bounds__(256) rmsnorm_kernel(
    const float* __restrict__ x, const float* __restrict__ w,
    float* __restrict__ o)
{
    int row = blockIdx.x;
    const float4* xr = (const float4*)(x + (size_t)row * DD);
    float4* orow = (float4*)(o + (size_t)row * DD);
    const float4* wr = (const float4*)w;
    int t = threadIdx.x;

    float4 v = xr[t];
    float ss = v.x * v.x + v.y * v.y + v.z * v.z + v.w * v.w;
#pragma unroll
    for (int off = 16; off > 0; off >>= 1)
        ss += __shfl_xor_sync(0xffffffffu, ss, off);

    __shared__ float red[8];
    __shared__ float stot;
    if ((t & 31) == 0) red[t >> 5] = ss;
    __syncthreads();
    if (t == 0) {
        float tot = 0.f;
#pragma unroll
        for (int i = 0; i < 8; i++) tot += red[i];
        stot = tot;
    }
    __syncthreads();

    float inv = rsqrtf(stot * (1.0f / DD) + 1e-6f);
    float4 wv = wr[t];
    float4 ov;
    ov.x = v.x * inv * wv.x;
    ov.y = v.y * inv * wv.y;
    ov.z = v.z * inv * wv.z;
    ov.w = v.w * inv * wv.w;
    orow[t] = ov;
}

// ---------------------------------------------------------------------------
// SGEMM: C[M,N] = A[M,K] @ W[N,K]^T (+ optional residual R[M,N])
// 128x128 block tile, BK=8, 256 threads, 8x8 microtile (FFMA2-packed),
// double-buffered smem. Requires M%128==0, N%128==0, K%8==0.
// ---------------------------------------------------------------------------
#define SPAD 132   // padded stride (128 + 4) to avoid STS bank conflicts

template <bool RES>
__global__ void __launch_bounds__(256, 2) sgemm128(
    const float* __restrict__ A, const float* __restrict__ W,
    float* __restrict__ C, const float* __restrict__ R,
    int N, int K)
{
    const int BM = 128, BN = 128, BK = 8;
    __shared__ float As[2][BK][SPAD];
    __shared__ float Bs[2][BK][SPAD];

    const int tid = threadIdx.x;
    const int m0 = blockIdx.y * BM;
    const int n0 = blockIdx.x * BN;

    // load mapping: 256 threads cover 128 rows x 8 k (one float4 each)
    const int lrow = tid >> 1;         // 0..127
    const int lk   = (tid & 1) * 4;    // 0 or 4
    const float* Ap = A + (size_t)(m0 + lrow) * K + lk;
    const float* Wp = W + (size_t)(n0 + lrow) * K + lk;

    // compute mapping: 8x8 microtile
    const int tx = tid & 15;           // n-group
    const int ty = tid >> 4;           // m-group

    // packed accumulators: acc2[i][jp] holds columns {2jp, 2jp+1} of row i
    unsigned long long acc2[8][4] = {};
    float4 av, wv;

    // preload tile 0
    av = *(const float4*)Ap;
    wv = *(const float4*)Wp;
    As[0][lk + 0][lrow] = av.x; As[0][lk + 1][lrow] = av.y;
    As[0][lk + 2][lrow] = av.z; As[0][lk + 3][lrow] = av.w;
    Bs[0][lk + 0][lrow] = wv.x; Bs[0][lk + 1][lrow] = wv.y;
    Bs[0][lk + 2][lrow] = wv.z; Bs[0][lk + 3][lrow] = wv.w;
    __syncthreads();

    int buf = 0;
    for (int k0 = BK; k0 <= K; k0 += BK) {
        const bool more = (k0 < K);
        if (more) {
            av = *(const float4*)(Ap + k0);
            wv = *(const float4*)(Wp + k0);
        }
#pragma unroll
        for (int kk = 0; kk < BK; kk++) {
            float a[8], b[8];
            *(float4*)(a)     = *(const float4*)&As[buf][kk][ty * 4];
            *(float4*)(a + 4) = *(const float4*)&As[buf][kk][ty * 4 + 64];
            *(float4*)(b)     = *(const float4*)&Bs[buf][kk][tx * 4];
            *(float4*)(b + 4) = *(const float4*)&Bs[buf][kk][tx * 4 + 64];
            unsigned long long B2[4];
#pragma unroll
            for (int jp = 0; jp < 4; jp++)
                B2[jp] = pack2(b[2 * jp], b[2 * jp + 1]);
#pragma unroll
            for (int i = 0; i < 8; i++) {
                unsigned long long A2 = pack2(a[i], a[i]);
#pragma unroll
                for (int jp = 0; jp < 4; jp++)
                    fma2(acc2[i][jp], A2, B2[jp]);
            }
        }
        if (more) {
            int nb = buf ^ 1;
            As[nb][lk + 0][lrow] = av.x; As[nb][lk + 1][lrow] = av.y;
            As[nb][lk + 2][lrow] = av.z; As[nb][lk + 3][lrow] = av.w;
            Bs[nb][lk + 0][lrow] = wv.x; Bs[nb][lk + 1][lrow] = wv.y;
            Bs[nb][lk + 2][lrow] = wv.z; Bs[nb][lk + 3][lrow] = wv.w;
            __syncthreads();
            buf = nb;
        }
    }

    // epilogue: 8x8 per thread = 2x2 grid of 4x4 float4 stores
#pragma unroll
    for (int ih = 0; ih < 2; ih++) {
#pragma unroll
        for (int i = 0; i < 4; i++) {
            int row = m0 + ih * 64 + ty * 4 + i;
#pragma unroll
            for (int jh = 0; jh < 2; jh++) {
                int col = n0 + jh * 64 + tx * 4;
                float4 cv;
                unpack2(acc2[ih * 4 + i][jh * 2 + 0], cv.x, cv.y);
                unpack2(acc2[ih * 4 + i][jh * 2 + 1], cv.z, cv.w);
                if (RES) {
                    float4 rv = *(const float4*)(R + (size_t)row * N + col);
                    cv.x += rv.x; cv.y += rv.y; cv.z += rv.z; cv.w += rv.w;
                }
                *(float4*)(C + (size_t)row * N + col) = cv;
            }
        }
    }
}

// ---------------------------------------------------------------------------
// Windowed attention.
// One block per (64-query tile, head, batch). Key union window = 192 keys.
// Dynamic smem: Qs[64][64] + Kt[64][193] + Vs[192][64] + S[64][192]
// ---------------------------------------------------------------------------
#define ATTN_SMEM ((64 * 64 + 64 * 193 + 192 * 64 + 64 * 192) * 4)

__global__ void __launch_bounds__(256) attn_kernel(
    const float* __restrict__ qkv, float* __restrict__ o)
{
    extern __shared__ float sm[];
    float* Qs = sm;                 // [r][d]   stride 64
    float* Kt = Qs + 64 * 64;       // [d][jj]  stride 193
    float* Vs = Kt + 64 * 193;      // [jj][d]  stride 64
    float* S  = Vs + 192 * 64;      // [r][jj]  stride 192

    const int q0 = blockIdx.x * 64;
    const int h  = blockIdx.y;
    const int b  = blockIdx.z;
    const int tid = threadIdx.x;

    // ---- load Q, K (transposed), V ----
    {
        int c4 = (tid & 15) * 4;
        int rb = tid >> 4;  // 0..15
#pragma unroll
        for (int p = 0; p < 4; p++) {
            int r = p * 16 + rb;
            float4 v = *(const float4*)(qkv +
                (size_t)(b * LL + q0 + r) * (3 * DD) + h * DH + c4);
            *(float4*)(Qs + r * 64 + c4) = v;
        }
#pragma unroll
        for (int p = 0; p < 12; p++) {
            int jj = p * 16 + rb;
            int j = q0 - HALF + jj;
            float4 kv = make_float4(0.f, 0.f, 0.f, 0.f);
            float4 vv = make_float4(0.f, 0.f, 0.f, 0.f);
            if (j >= 0 && j < LL) {
                const float* base = qkv + (size_t)(b * LL + j) * (3 * DD) + h * DH + c4;
                kv = *(const float4*)(base + DD);
                vv = *(const float4*)(base + 2 * DD);
            }
            Kt[(c4 + 0) * 193 + jj] = kv.x;
            Kt[(c4 + 1) * 193 + jj] = kv.y;
            Kt[(c4 + 2) * 193 + jj] = kv.z;
            Kt[(c4 + 3) * 193 + jj] = kv.w;
            *(float4*)(Vs + jj * 64 + c4) = vv;
        }
    }
    __syncthreads();

    // ---- scores S[64][192] = (Q @ K^T) / 8, masked ----
    {
        int rowg = tid >> 4;   // rows rowg*4..+3
        int colg = tid & 15;   // cols colg*12..+11
        float acc[4][12] = {};
#pragma unroll 4
        for (int d = 0; d < 64; d++) {
            float qv[4];
#pragma unroll
            for (int i = 0; i < 4; i++) qv[i] = Qs[(rowg * 4 + i) * 64 + d];
            float kva[12];
#pragma unroll
            for (int c = 0; c < 12; c++) kva[c] = Kt[d * 193 + colg * 12 + c];
#pragma unroll
            for (int i = 0; i < 4; i++)
#pragma unroll
                for (int c = 0; c < 12; c++)
                    acc[i][c] = fmaf(qv[i], kva[c], acc[i][c]);
        }
        const float scale = 0.125f;  // 1/sqrt(64)
#pragma unroll
        for (int i = 0; i < 4; i++) {
            int r = rowg * 4 + i;
#pragma unroll
            for (int c = 0; c < 12; c++) {
                int jj = colg * 12 + c;
                int j = q0 - HALF + jj;
                bool valid = (j >= 0) && (j < LL) && (jj >= r) && (jj <= r + 2 * HALF);
                S[r * 192 + jj] = valid ? acc[i][c] * scale : -1e30f;
            }
        }
    }
    __syncthreads();

    // ---- softmax per row (8 warps x 8 rows) ----
    {
        int w = tid >> 5, lane = tid & 31;
#pragma unroll
        for (int rr = 0; rr < 8; rr++) {
            int r = w * 8 + rr;
            float vv[6];
            float mx = -1e30f;
#pragma unroll
            for (int s = 0; s < 6; s++) {
                vv[s] = S[r * 192 + lane + 32 * s];
                mx = fmaxf(mx, vv[s]);
            }
#pragma unroll
            for (int off = 16; off > 0; off >>= 1)
                mx = fmaxf(mx, __shfl_xor_sync(0xffffffffu, mx, off));
            float sum = 0.f;
#pragma unroll
            for (int s = 0; s < 6; s++) {
                vv[s] = __expf(vv[s] - mx);
                sum += vv[s];
            }
#pragma unroll
            for (int off = 16; off > 0; off >>= 1)
                sum += __shfl_xor_sync(0xffffffffu, sum, off);
            float inv = 1.0f / sum;
#pragma unroll
            for (int s = 0; s < 6; s++)
                S[r * 192 + lane + 32 * s] = vv[s] * inv;
        }
    }
    __syncthreads();

    // ---- O[64][64] = P @ V ----
    {
        int ty = tid >> 4, tx = tid & 15;
        float acc[4][4] = {};
#pragma unroll 2
        for (int jj = 0; jj < 192; jj++) {
            float p[4];
#pragma unroll
            for (int i = 0; i < 4; i++) p[i] = S[(ty * 4 + i) * 192 + jj];
            float4 v = *(const float4*)(Vs + jj * 64 + tx * 4);
            float vr[4] = {v.x, v.y, v.z, v.w};
#pragma unroll
            for (int i = 0; i < 4; i++)
#pragma unroll
                for (int j = 0; j < 4; j++)
                    acc[i][j] = fmaf(p[i], vr[j], acc[i][j]);
        }
#pragma unroll
        for (int i = 0; i < 4; i++) {
            int r = q0 + ty * 4 + i;
            *(float4*)(o + (size_t)(b * LL + r) * DD + h * DH + tx * 4) =
                make_float4(acc[i][0], acc[i][1], acc[i][2], acc[i][3]);
        }
    }
}

// ---------------------------------------------------------------------------
extern "C" void kernel_launch(void* const* d_in, const int* in_sizes, int n_in,
                              void* d_out, int out_size)
{
    const float* x     = (const float*)d_in[0];
    const float* wnorm = (const float*)d_in[1];
    const float* wqkv  = (const float*)d_in[2];
    const float* wout  = (const float*)d_in[3];
    float* out = (float*)d_out;

    float* xn   = nullptr;
    float* qkv  = nullptr;
    float* attn = nullptr;
    cudaGetSymbolAddress((void**)&xn,   g_xn);
    cudaGetSymbolAddress((void**)&qkv,  g_qkv);
    cudaGetSymbolAddress((void**)&attn, g_attn);

    cudaFuncSetAttribute(attn_kernel,
                         cudaFuncAttributeMaxDynamicSharedMemorySize, ATTN_SMEM);

    // 1) RMSNorm
    rmsnorm_kernel<<<NTOK, 256>>>(x, wnorm, xn);

    // 2) QKV projection: [4096,1024] @ [3072,1024]^T -> [4096,3072]
    {
        dim3 grid(3 * DD / 128, NTOK / 128);
        sgemm128<false><<<grid, 256>>>(xn, wqkv, qkv, nullptr, 3 * DD, DD);
    }

    // 3) Windowed attention
    {
        dim3 grid(LL / 64, HH, BB);
        attn_kernel<<<grid, 256, ATTN_SMEM>>>(qkv, attn);
    }

    // 4) Output projection + residual: [4096,1024] @ [1024,1024]^T + x
    {
        dim3 grid(DD / 128, NTOK / 128);
        sgemm128<true><<<grid, 256>>>(attn, wout, out, x, DD, DD);
    }
}

// round 17
// speedup vs baseline: 1.6049x; 1.3063x over previous
#include <cuda_runtime.h>
#include <cuda_bf16.h>
#include <stdint.h>
#include <math.h>

// Problem constants (fixed by the dataset)
#define BB 2
#define LL 2048
#define DD 1024
#define HH 16
#define DH 64
#define HALF 64          // window_size / 2
#define NTOK (BB * LL)   // 4096
#define KCAT 3072        // 3 * DD (bf16-split concatenated K)
#define NCH (KCAT / 32)  // 96 chunks of 32 bf16

// Scratch (no cudaMalloc allowed)
__device__ __align__(128) float g_qkv[NTOK * 3 * DD];            // 48 MB
__device__ __align__(128) float g_attn[NTOK * DD];               // 16 MB
__device__ __align__(128) unsigned short g_acat[NTOK * KCAT];    // 24 MB bf16
__device__ __align__(128) unsigned short g_bcat[3 * DD * KCAT];  // 18.9 MB bf16

// ===========================================================================
// Warp-MMA helpers (base ISA: ldmatrix + mma.sync — compiles for sm_103)
// ===========================================================================
__device__ __forceinline__ uint32_t smem_u32(const void* p) {
    uint32_t a;
    asm("{ .reg .u64 t; cvta.to.shared.u64 t, %1; cvt.u32.u64 %0, t; }"
        : "=r"(a) : "l"(p));
    return a;
}

__device__ __forceinline__ void ldm_x4(uint32_t* r, uint32_t addr) {
    asm volatile("ldmatrix.sync.aligned.m8n8.x4.shared.b16 {%0,%1,%2,%3}, [%4];"
                 : "=r"(r[0]), "=r"(r[1]), "=r"(r[2]), "=r"(r[3]) : "r"(addr));
}

__device__ __forceinline__ void mma16816(float* d, const uint32_t* a,
                                         uint32_t b0, uint32_t b1) {
    asm volatile(
        "mma.sync.aligned.m16n8k16.row.col.f32.bf16.bf16.f32 "
        "{%0,%1,%2,%3}, {%4,%5,%6,%7}, {%8,%9}, {%0,%1,%2,%3};"
        : "+f"(d[0]), "+f"(d[1]), "+f"(d[2]), "+f"(d[3])
        : "r"(a[0]), "r"(a[1]), "r"(a[2]), "r"(a[3]), "r"(b0), "r"(b1));
}

// ===========================================================================
// RMSNorm fused with bf16 hi/lo split into A_cat layout [hi | lo | hi]
// ===========================================================================
__global__ void __launch_bounds__(256) rmsnorm_acat_kernel(
    const float* __restrict__ x, const float* __restrict__ w,
    unsigned short* __restrict__ acat)
{
    int row = blockIdx.x;
    const float4* xr = (const float4*)(x + (size_t)row * DD);
    const float4* wr = (const float4*)w;
    int t = threadIdx.x;

    float4 v = xr[t];
    float ss = v.x * v.x + v.y * v.y + v.z * v.z + v.w * v.w;
#pragma unroll
    for (int off = 16; off > 0; off >>= 1)
        ss += __shfl_xor_sync(0xffffffffu, ss, off);

    __shared__ float red[8];
    __shared__ float stot;
    if ((t & 31) == 0) red[t >> 5] = ss;
    __syncthreads();
    if (t == 0) {
        float tot = 0.f;
#pragma unroll
        for (int i = 0; i < 8; i++) tot += red[i];
        stot = tot;
    }
    __syncthreads();

    float inv = rsqrtf(stot * (1.0f / DD) + 1e-6f);
    float4 wv = wr[t];
    float xn[4] = {v.x * inv * wv.x, v.y * inv * wv.y,
                   v.z * inv * wv.z, v.w * inv * wv.w};
    __nv_bfloat16* a = (__nv_bfloat16*)(acat + (size_t)row * KCAT + t * 4);
#pragma unroll
    for (int i = 0; i < 4; i++) {
        __nv_bfloat16 hi = __float2bfloat16(xn[i]);
        __nv_bfloat16 lo = __float2bfloat16(xn[i] - __bfloat162float(hi));
        a[i] = hi;
        a[DD + i] = lo;
        a[2 * DD + i] = hi;
    }
}

// Decompose fp32 activations -> A_cat [hi | lo | hi]. One block per row.
__global__ void __launch_bounds__(256) decomp_a_kernel(
    const float* __restrict__ src, unsigned short* __restrict__ acat)
{
    int row = blockIdx.x;
    int t = threadIdx.x;
    float4 v = *(const float4*)(src + (size_t)row * DD + t * 4);
    float xv[4] = {v.x, v.y, v.z, v.w};
    __nv_bfloat16* a = (__nv_bfloat16*)(acat + (size_t)row * KCAT + t * 4);
#pragma unroll
    for (int i = 0; i < 4; i++) {
        __nv_bfloat16 hi = __float2bfloat16(xv[i]);
        __nv_bfloat16 lo = __float2bfloat16(xv[i] - __bfloat162float(hi));
        a[i] = hi;
        a[DD + i] = lo;
        a[2 * DD + i] = hi;
    }
}

// Decompose fp32 weights -> B_cat [hi | hi | lo]. One block per row (N rows).
__global__ void __launch_bounds__(256) decomp_w_kernel(
    const float* __restrict__ src, unsigned short* __restrict__ bcat)
{
    int row = blockIdx.x;
    int t = threadIdx.x;
    float4 v = *(const float4*)(src + (size_t)row * DD + t * 4);
    float xv[4] = {v.x, v.y, v.z, v.w};
    __nv_bfloat16* b = (__nv_bfloat16*)(bcat + (size_t)row * KCAT + t * 4);
#pragma unroll
    for (int i = 0; i < 4; i++) {
        __nv_bfloat16 hi = __float2bfloat16(xv[i]);
        __nv_bfloat16 lo = __float2bfloat16(xv[i] - __bfloat162float(hi));
        b[i] = hi;
        b[DD + i] = hi;
        b[2 * DD + i] = lo;
    }
}

// ===========================================================================
// mma.sync bf16 GEMM: C[M,N] = Acat[M,KCAT] @ Bcat[N,KCAT]^T (+ residual)
// 128x128 tile, BK=32 bf16, 8 warps (2x4), warp tile 64x32, double-buffered.
// smem rows: 32 bf16 = 64 B data, 80 B stride (conflict-free ldmatrix).
// ===========================================================================
#define ROWB 80   // smem row stride in bytes

template <bool RES>
__global__ void __launch_bounds__(256) gemm_mma(
    const unsigned short* __restrict__ Acat,
    const unsigned short* __restrict__ Bcat,
    float* __restrict__ C, const float* __restrict__ R, int N)
{
    __shared__ __align__(128) char As[2][128 * ROWB];
    __shared__ __align__(128) char Bs[2][128 * ROWB];

    const int tid = threadIdx.x;
    const int wid = tid >> 5;
    const int lane = tid & 31;
    const int m0 = blockIdx.y * 128;
    const int n0 = blockIdx.x * 128;
    const int wm = wid >> 2;        // 0..1
    const int wn = wid & 3;         // 0..3

    // gmem load mapping: thread covers row = tid/2, 32 B segment = (tid&1)*32 B
    const int lrow = tid >> 1;
    const int lseg = (tid & 1) * 2;             // in uint4 units
    const uint4* agp = (const uint4*)(Acat + (size_t)(m0 + lrow) * KCAT);
    const uint4* bgp = (const uint4*)(Bcat + (size_t)(n0 + lrow) * KCAT);
    const uint32_t s_off = (uint32_t)(lrow * ROWB + (tid & 1) * 32);

    uint32_t asb[2] = {smem_u32(As[0]), smem_u32(As[1])};
    uint32_t bsb[2] = {smem_u32(Bs[0]), smem_u32(Bs[1])};

    // per-lane ldmatrix address components
    const int a_rin = ((lane >> 3) & 1) * 8 + (lane & 7);
    const int a_kb = (lane >> 4) * 16;
    const uint32_t a_base_off = (uint32_t)((wm * 64 + a_rin) * ROWB + a_kb);
    const uint32_t b_base_off = (uint32_t)((wn * 32 + lane) * ROWB);

    float acc[4][4][4] = {};

    // preload chunk 0
    {
        uint4 pa0 = agp[lseg], pa1 = agp[lseg + 1];
        uint4 pb0 = bgp[lseg], pb1 = bgp[lseg + 1];
        *(uint4*)(As[0] + s_off) = pa0;
        *(uint4*)(As[0] + s_off + 16) = pa1;
        *(uint4*)(Bs[0] + s_off) = pb0;
        *(uint4*)(Bs[0] + s_off + 16) = pb1;
    }
    __syncthreads();

    for (int c = 0; c < NCH; c++) {
        const int buf = c & 1;
        uint4 pa0, pa1, pb0, pb1;
        const bool more = (c + 1 < NCH);
        if (more) {
            int gi = (c + 1) * 4 + lseg;
            pa0 = agp[gi]; pa1 = agp[gi + 1];
            pb0 = bgp[gi]; pb1 = bgp[gi + 1];
        }

        // compute on current buffer: 2 k16 steps
#pragma unroll
        for (int ks = 0; ks < 2; ks++) {
            uint32_t afr[4][4];
#pragma unroll
            for (int fm = 0; fm < 4; fm++)
                ldm_x4(afr[fm], asb[buf] + a_base_off + fm * 16 * ROWB + ks * 32);
            uint32_t bfr0[4], bfr1[4];
            ldm_x4(bfr0, bsb[buf] + b_base_off + ks * 32);
            ldm_x4(bfr1, bsb[buf] + b_base_off + ks * 32 + 16);
#pragma unroll
            for (int fm = 0; fm < 4; fm++)
#pragma unroll
                for (int fn = 0; fn < 4; fn++)
                    mma16816(acc[fm][fn], afr[fm], bfr0[fn], bfr1[fn]);
        }

        if (more) {
            int nb = buf ^ 1;
            *(uint4*)(As[nb] + s_off) = pa0;
            *(uint4*)(As[nb] + s_off + 16) = pa1;
            *(uint4*)(Bs[nb] + s_off) = pb0;
            *(uint4*)(Bs[nb] + s_off + 16) = pb1;
        }
        __syncthreads();
    }

    // epilogue: acc[fm][fn] fragment -> C rows m0+wm*64+fm*16+{gid, gid+8},
    // cols n0+wn*32+fn*8+(lane&3)*2
    const int gid = lane >> 2;
    const int cph = (lane & 3) * 2;
#pragma unroll
    for (int fm = 0; fm < 4; fm++) {
        int r0 = m0 + wm * 64 + fm * 16 + gid;
        int r1 = r0 + 8;
#pragma unroll
        for (int fn = 0; fn < 4; fn++) {
            int col = n0 + wn * 32 + fn * 8 + cph;
            float2 v0 = make_float2(acc[fm][fn][0], acc[fm][fn][1]);
            float2 v1 = make_float2(acc[fm][fn][2], acc[fm][fn][3]);
            if (RES) {
                float2 q0 = *(const float2*)(R + (size_t)r0 * N + col);
                float2 q1 = *(const float2*)(R + (size_t)r1 * N + col);
                v0.x += q0.x; v0.y += q0.y;
                v1.x += q1.x; v1.y += q1.y;
            }
            *(float2*)(C + (size_t)r0 * N + col) = v0;
            *(float2*)(C + (size_t)r1 * N + col) = v1;
        }
    }
}

// ===========================================================================
// Windowed attention (fp32, unchanged — known good)
// ===========================================================================
#define ATTN_SMEM ((64 * 64 + 64 * 193 + 192 * 64 + 64 * 192) * 4)

__global__ void __launch_bounds__(256) attn_kernel(
    const float* __restrict__ qkv, float* __restrict__ o)
{
    extern __shared__ float smf[];
    float* Qs = smf;                // [r][d]   stride 64
    float* Kt = Qs + 64 * 64;       // [d][jj]  stride 193
    float* Vs = Kt + 64 * 193;      // [jj][d]  stride 64
    float* S  = Vs + 192 * 64;      // [r][jj]  stride 192

    const int q0 = blockIdx.x * 64;
    const int h  = blockIdx.y;
    const int b  = blockIdx.z;
    const int tid = threadIdx.x;

    {
        int c4 = (tid & 15) * 4;
        int rb = tid >> 4;
#pragma unroll
        for (int p = 0; p < 4; p++) {
            int r = p * 16 + rb;
            float4 v = *(const float4*)(qkv +
                (size_t)(b * LL + q0 + r) * (3 * DD) + h * DH + c4);
            *(float4*)(Qs + r * 64 + c4) = v;
        }
#pragma unroll
        for (int p = 0; p < 12; p++) {
            int jj = p * 16 + rb;
            int j = q0 - HALF + jj;
            float4 kv = make_float4(0.f, 0.f, 0.f, 0.f);
            float4 vv = make_float4(0.f, 0.f, 0.f, 0.f);
            if (j >= 0 && j < LL) {
                const float* base = qkv + (size_t)(b * LL + j) * (3 * DD) + h * DH + c4;
                kv = *(const float4*)(base + DD);
                vv = *(const float4*)(base + 2 * DD);
            }
            Kt[(c4 + 0) * 193 + jj] = kv.x;
            Kt[(c4 + 1) * 193 + jj] = kv.y;
            Kt[(c4 + 2) * 193 + jj] = kv.z;
            Kt[(c4 + 3) * 193 + jj] = kv.w;
            *(float4*)(Vs + jj * 64 + c4) = vv;
        }
    }
    __syncthreads();

    {
        int rowg = tid >> 4;
        int colg = tid & 15;
        float acc[4][12] = {};
#pragma unroll 4
        for (int d = 0; d < 64; d++) {
            float qv[4];
#pragma unroll
            for (int i = 0; i < 4; i++) qv[i] = Qs[(rowg * 4 + i) * 64 + d];
            float kva[12];
#pragma unroll
            for (int c = 0; c < 12; c++) kva[c] = Kt[d * 193 + colg * 12 + c];
#pragma unroll
            for (int i = 0; i < 4; i++)
#pragma unroll
                for (int c = 0; c < 12; c++)
                    acc[i][c] = fmaf(qv[i], kva[c], acc[i][c]);
        }
        const float scale = 0.125f;
#pragma unroll
        for (int i = 0; i < 4; i++) {
            int r = rowg * 4 + i;
#pragma unroll
            for (int c = 0; c < 12; c++) {
                int jj = colg * 12 + c;
                int j = q0 - HALF + jj;
                bool valid = (j >= 0) && (j < LL) && (jj >= r) && (jj <= r + 2 * HALF);
                S[r * 192 + jj] = valid ? acc[i][c] * scale : -1e30f;
            }
        }
    }
    __syncthreads();

    {
        int w = tid >> 5, lane = tid & 31;
#pragma unroll
        for (int rr = 0; rr < 8; rr++) {
            int r = w * 8 + rr;
            float vv[6];
            float mx = -1e30f;
#pragma unroll
            for (int s = 0; s < 6; s++) {
                vv[s] = S[r * 192 + lane + 32 * s];
                mx = fmaxf(mx, vv[s]);
            }
#pragma unroll
            for (int off = 16; off > 0; off >>= 1)
                mx = fmaxf(mx, __shfl_xor_sync(0xffffffffu, mx, off));
            float sum = 0.f;
#pragma unroll
            for (int s = 0; s < 6; s++) {
                vv[s] = __expf(vv[s] - mx);
                sum += vv[s];
            }
#pragma unroll
            for (int off = 16; off > 0; off >>= 1)
                sum += __shfl_xor_sync(0xffffffffu, sum, off);
            float inv = 1.0f / sum;
#pragma unroll
            for (int s = 0; s < 6; s++)
                S[r * 192 + lane + 32 * s] = vv[s] * inv;
        }
    }
    __syncthreads();

    {
        int ty = tid >> 4, tx = tid & 15;
        float acc[4][4] = {};
#pragma unroll 2
        for (int jj = 0; jj < 192; jj++) {
            float p[4];
#pragma unroll
            for (int i = 0; i < 4; i++) p[i] = S[(ty * 4 + i) * 192 + jj];
            float4 v = *(const float4*)(Vs + jj * 64 + tx * 4);
            float vr[4] = {v.x, v.y, v.z, v.w};
#pragma unroll
            for (int i = 0; i < 4; i++)
#pragma unroll
                for (int j = 0; j < 4; j++)
                    acc[i][j] = fmaf(p[i], vr[j], acc[i][j]);
        }
#pragma unroll
        for (int i = 0; i < 4; i++) {
            int r = q0 + ty * 4 + i;
            *(float4*)(o + (size_t)(b * LL + r) * DD + h * DH + tx * 4) =
                make_float4(acc[i][0], acc[i][1], acc[i][2], acc[i][3]);
        }
    }
}

// ===========================================================================
extern "C" void kernel_launch(void* const* d_in, const int* in_sizes, int n_in,
                              void* d_out, int out_size)
{
    const float* x     = (const float*)d_in[0];
    const float* wnorm = (const float*)d_in[1];
    const float* wqkv  = (const float*)d_in[2];
    const float* wout  = (const float*)d_in[3];
    float* out = (float*)d_out;

    float* qkv = nullptr;
    float* attn = nullptr;
    unsigned short* acat = nullptr;
    unsigned short* bcat = nullptr;
    cudaGetSymbolAddress((void**)&qkv,  g_qkv);
    cudaGetSymbolAddress((void**)&attn, g_attn);
    cudaGetSymbolAddress((void**)&acat, g_acat);
    cudaGetSymbolAddress((void**)&bcat, g_bcat);

    cudaFuncSetAttribute(attn_kernel,
                         cudaFuncAttributeMaxDynamicSharedMemorySize, ATTN_SMEM);

    // 1) RMSNorm + split -> A_cat;  split w_qkv -> B_cat
    rmsnorm_acat_kernel<<<NTOK, 256>>>(x, wnorm, acat);
    decomp_w_kernel<<<3 * DD, 256>>>(wqkv, bcat);

    // 2) QKV projection on tensor cores (HMMA): [4096,3072cat] x [3072,3072cat]
    {
        dim3 grid(3 * DD / 128, NTOK / 128);
        gemm_mma<false><<<grid, 256>>>(acat, bcat, qkv, nullptr, 3 * DD);
    }

    // 3) Windowed attention (fp32)
    {
        dim3 grid(LL / 64, HH, BB);
        attn_kernel<<<grid, 256, ATTN_SMEM>>>(qkv, attn);
    }

    // 4) Split attn -> A_cat, w_out -> B_cat; out projection + residual
    decomp_a_kernel<<<NTOK, 256>>>(attn, acat);
    decomp_w_kernel<<<DD, 256>>>(wout, bcat);
    {
        dim3 grid(DD / 128, NTOK / 128);
        gemm_mma<true><<<grid, 256>>>(acat, bcat, out, x, DD);
    }
}